// round 1
// baseline (speedup 1.0000x reference)
#include <cuda_runtime.h>

// LSTMCell: z = x@Wx + bx + h@Wh + bh ; gates -> C_new, h_new
// Fused as one GEMM [32768 x 1024] * [1024 x 2048] with gate-interleaved
// weight permutation so the epilogue is tile-local.

#define NB    32768
#define DH    512
#define FOURH 2048
#define KTOT  1024
#define NKB   64          // KTOT / BK

#define BM 128
#define BN 128
#define BK 16
#define AST 20            // A smem row stride (pad for conflict-free frag loads)
#define BST 136           // B smem row stride (stride%32==8 -> conflict-free)
#define EST 132           // epilogue smem stride
#define B_OFF (2*BM*AST)  // 5120 floats
#define SMEM_FLOATS (2*BM*AST + 2*BK*BST)  // 9472 floats = 37.9 KB

__device__ float g_Wp[KTOT * FOURH];  // gate-interleaved, tf32-rounded weights
__device__ float g_bp[FOURH];         // combined gate-interleaved bias

__device__ __forceinline__ float tf32r(float x) {
    float r; asm("cvt.rna.tf32.f32 %0, %1;" : "=f"(r) : "f"(x)); return r;
}
__device__ __forceinline__ float tanh_fast(float x) {
    float r; asm("tanh.approx.f32 %0, %1;" : "=f"(r) : "f"(x)); return r;
}
__device__ __forceinline__ float sig_fast(float x) {
    return 0.5f * tanh_fast(0.5f * x) + 0.5f;
}

// Build Wp[k][4*j+g] = W[k][g*512+j] (tf32-rounded) and bp[4*j+g] = bx+bh.
__global__ void prep_kernel(const float* __restrict__ Wx, const float* __restrict__ Wh,
                            const float* __restrict__ bx, const float* __restrict__ bh) {
    int idx = blockIdx.x * 256 + threadIdx.x;
    if (idx < KTOT * FOURH) {
        int k = idx >> 11;          // / 2048
        int c = idx & 2047;
        int j = c >> 2, g = c & 3;
        float v = (k < DH) ? Wx[k * FOURH + g * DH + j]
                           : Wh[(k - DH) * FOURH + g * DH + j];
        g_Wp[idx] = tf32r(v);
    }
    if (idx < FOURH) {
        int j = idx >> 2, g = idx & 3;
        g_bp[idx] = bx[g * DH + j] + bh[g * DH + j];
    }
}

__global__ void __launch_bounds__(256, 2)
lstm_kernel(const float* __restrict__ x, const float* __restrict__ h,
            const float* __restrict__ Cin, float* __restrict__ out) {
    __shared__ float smem[SMEM_FLOATS];

    const int tid    = threadIdx.x;
    const int lane   = tid & 31;
    const int wid    = tid >> 5;
    const int warp_m = wid & 1;    // 0..1 : 64-row halves
    const int warp_n = wid >> 1;   // 0..3 : 32-col slices
    const int m0 = blockIdx.y * BM;
    const int n0 = blockIdx.x * BN;

    float acc[4][4][4];
#pragma unroll
    for (int a = 0; a < 4; a++)
#pragma unroll
        for (int b = 0; b < 4; b++)
#pragma unroll
            for (int c = 0; c < 4; c++) acc[a][b][c] = 0.f;

    // per-thread staging indices
    const int arow0 = tid >> 2;   // + 64 for second chunk
    const int acq   = tid & 3;
    const int bkr0  = tid >> 5;   // + 8 for second chunk
    const int bcq   = tid & 31;

    float4 aR0, aR1, bR0, bR1;

    auto LOADG = [&](int kb) {
        const float* Ap  = (kb < 32) ? x : h;
        const int kcol   = (kb & 31) * BK;
        aR0 = *(const float4*)&Ap[(m0 + arow0)      * DH + kcol + acq * 4];
        aR1 = *(const float4*)&Ap[(m0 + arow0 + 64) * DH + kcol + acq * 4];
        const float* Bp = g_Wp + (size_t)(kb * BK) * FOURH + n0;
        bR0 = *(const float4*)&Bp[(size_t)(bkr0)     * FOURH + bcq * 4];
        bR1 = *(const float4*)&Bp[(size_t)(bkr0 + 8) * FOURH + bcq * 4];
    };

    auto STORES = [&](int buf) {
        float* A  = smem + buf * BM * AST;
        float* Bm = smem + B_OFF + buf * BK * BST;
        float* a0 = A + arow0 * AST + acq * 4;
        a0[0] = tf32r(aR0.x); a0[1] = tf32r(aR0.y); a0[2] = tf32r(aR0.z); a0[3] = tf32r(aR0.w);
        float* a1 = A + (arow0 + 64) * AST + acq * 4;
        a1[0] = tf32r(aR1.x); a1[1] = tf32r(aR1.y); a1[2] = tf32r(aR1.z); a1[3] = tf32r(aR1.w);
        float* b0 = Bm + bkr0 * BST + bcq * 4;
        b0[0] = bR0.x; b0[1] = bR0.y; b0[2] = bR0.z; b0[3] = bR0.w;
        float* b1 = Bm + (bkr0 + 8) * BST + bcq * 4;
        b1[0] = bR1.x; b1[1] = bR1.y; b1[2] = bR1.z; b1[3] = bR1.w;
    };

    auto COMPUTE = [&](int buf) {
        const float* A  = smem + buf * BM * AST;
        const float* Bm = smem + B_OFF + buf * BK * BST;
#pragma unroll
        for (int ks = 0; ks < 2; ks++) {
            const int k0 = ks * 8;
            unsigned af[4][2 * 2], bf[4][2];
#pragma unroll
            for (int mi = 0; mi < 4; mi++) {
                const float* p = A + (warp_m * 64 + mi * 16 + (lane >> 2)) * AST
                                   + k0 + (lane & 3);
                af[mi][0] = __float_as_uint(p[0]);
                af[mi][1] = __float_as_uint(p[8 * AST]);
                af[mi][2] = __float_as_uint(p[4]);
                af[mi][3] = __float_as_uint(p[8 * AST + 4]);
            }
#pragma unroll
            for (int ni = 0; ni < 4; ni++) {
                const float* p = Bm + (k0 + (lane & 3)) * BST
                                    + warp_n * 32 + ni * 8 + (lane >> 2);
                bf[ni][0] = __float_as_uint(p[0]);
                bf[ni][1] = __float_as_uint(p[4 * BST]);
            }
#pragma unroll
            for (int mi = 0; mi < 4; mi++)
#pragma unroll
                for (int ni = 0; ni < 4; ni++)
                    asm volatile(
                        "mma.sync.aligned.m16n8k8.row.col.f32.tf32.tf32.f32 "
                        "{%0,%1,%2,%3},{%4,%5,%6,%7},{%8,%9},{%0,%1,%2,%3};"
                        : "+f"(acc[mi][ni][0]), "+f"(acc[mi][ni][1]),
                          "+f"(acc[mi][ni][2]), "+f"(acc[mi][ni][3])
                        : "r"(af[mi][0]), "r"(af[mi][1]), "r"(af[mi][2]), "r"(af[mi][3]),
                          "r"(bf[ni][0]), "r"(bf[ni][1]));
        }
    };

    // ---- mainloop: double-buffered ----
    LOADG(0);
    STORES(0);
    __syncthreads();
#pragma unroll 1
    for (int kb = 0; kb < NKB; kb++) {
        if (kb + 1 < NKB) LOADG(kb + 1);
        COMPUTE(kb & 1);
        __syncthreads();
        if (kb + 1 < NKB) {
            STORES((kb + 1) & 1);
            __syncthreads();
        }
    }

    // ---- fused epilogue: gates are adjacent columns (4j..4j+3) ----
    const int jl  = tid & 31;
    const int hid = (n0 >> 2) + jl;
    const float4 bias = *(const float4*)&g_bp[n0 + 4 * jl];

#pragma unroll
    for (int p = 0; p < 2; p++) {
        __syncthreads();
        if (warp_m == p) {
#pragma unroll
            for (int mi = 0; mi < 4; mi++)
#pragma unroll
                for (int ni = 0; ni < 4; ni++) {
                    int rl = mi * 16 + (lane >> 2);
                    int c  = warp_n * 32 + ni * 8 + 2 * (lane & 3);
                    smem[rl * EST + c]           = acc[mi][ni][0];
                    smem[rl * EST + c + 1]       = acc[mi][ni][1];
                    smem[(rl + 8) * EST + c]     = acc[mi][ni][2];
                    smem[(rl + 8) * EST + c + 1] = acc[mi][ni][3];
                }
        }
        __syncthreads();
#pragma unroll
        for (int it = 0; it < 8; it++) {
            int rl  = (tid >> 5) + 8 * it;
            int row = m0 + p * 64 + rl;
            float4 z = *(const float4*)&smem[rl * EST + 4 * jl];
            float iv = sig_fast(z.x + bias.x);
            float fv = sig_fast(z.y + bias.y);
            float ov = sig_fast(z.z + bias.z);
            float gv = tanh_fast(z.w + bias.w);
            float Cn = fv * Cin[(size_t)row * DH + hid] + iv * gv;
            float hn = ov * tanh_fast(Cn);
            out[(size_t)row * DH + hid]                      = Cn;
            out[(size_t)NB * DH + (size_t)row * DH + hid]    = hn;
        }
    }
}

extern "C" void kernel_launch(void* const* d_in, const int* in_sizes, int n_in,
                              void* d_out, int out_size) {
    const float* x  = (const float*)d_in[0];
    const float* C  = (const float*)d_in[1];
    const float* h  = (const float*)d_in[2];
    const float* Wx = (const float*)d_in[3];
    const float* bx = (const float*)d_in[4];
    const float* Wh = (const float*)d_in[5];
    const float* bh = (const float*)d_in[6];

    prep_kernel<<<(KTOT * FOURH + 255) / 256, 256>>>(Wx, Wh, bx, bh);

    dim3 grid(FOURH / BN, NB / BM);  // (16, 256) — x-fastest keeps A tile hot in L2
    lstm_kernel<<<grid, 256>>>(x, h, C, (float*)d_out);
}